// round 10
// baseline (speedup 1.0000x reference)
#include <cuda_runtime.h>
#include <cuda_bf16.h>
#include <math.h>
#include <stdint.h>

#define B_ROWS 8192
#define OBS    128
#define HID    512
#define HEADS  4
#define VSZ    256
#define NU     64
#define TOPK   8
#define NOPT   16

// ---------------- device scratch (static, allocation-free) ----------------
__device__ float g_weff[OBS * VSZ];   // 128x256 = pre_fc_w @ wbar
__device__ float g_c0[VSZ];           // pre_fc_b . wbar[:,v] + bbar[v]
__device__ float g_bb[VSZ];           // head-mean of value_b
__device__ float g_A[NOPT];
__device__ float g_C[NOPT];

// ===================== K1: fused prep ======================================
// grid (8 vt, 17): rt 0..15 -> W_eff 8 rows x 32 cols (K=512 in 4 chunks,
// LDG staging software-pipelined, 4 split accumulators). rt==0 also does c0.
// (vt==0, rt==16) -> per-option top-k scalars.
#define BSX 33    // bank(33k+c) = (k+c) mod 32 -> conflict-free
#define PKC 128   // K chunk
__global__ __launch_bounds__(256)
void prep_all(const float* __restrict__ value_w,
              const float* __restrict__ value_b,
              const float* __restrict__ pfw,
              const float* __restrict__ pfb,
              const float* __restrict__ p_w,
              const float* __restrict__ p_b) {
    int vt = blockIdx.x, rt = blockIdx.y;
    int t = threadIdx.x;

    if (rt == 16) {
        if (vt != 0) return;
        int lane = t & 31, w = t >> 5;
        for (int o = w; o < NOPT; o += 8) {
            float v0 = p_w[o * NU + lane] + p_b[lane];
            float v1 = p_w[o * NU + 32 + lane] + p_b[32 + lane];
            float ssum = 0.f;
#pragma unroll
            for (int it = 0; it < TOPK; it++) {
                float mv; int mi;
                if (v0 >= v1) { mv = v0; mi = lane; } else { mv = v1; mi = lane + 32; }
#pragma unroll
                for (int off = 16; off; off >>= 1) {
                    float ov = __shfl_xor_sync(0xffffffffu, mv, off);
                    int   oi = __shfl_xor_sync(0xffffffffu, mi, off);
                    if (ov > mv || (ov == mv && oi < mi)) { mv = ov; mi = oi; }
                }
                ssum += 1.f / (1.f + expf(-mv));
                if (mi == lane)           v0 = -1e30f;
                else if (mi == lane + 32) v1 = -1e30f;
            }
            if (lane == 0) {
                g_A[o] = ssum * (1.f / 64.f);
                g_C[o] = (8.f - ssum) * (1.f / 64.f);
            }
        }
        return;
    }

    __shared__ float as[8][PKC + 4];
    __shared__ float bs[PKC * BSX];
    __shared__ float red[256];

    bool do_c0 = (rt == 0);
    int r = t >> 5, c = t & 31;
    int sidx_k  = t >> 3;               // staging row base (x4 iters of +32)
    int sidx_c4 = (t & 7) << 2;

    // register staging buffers (pipelined LDG)
    float4 vbuf[4][4];                  // [i][head]
    float4 abuf;

    // ---- preload chunk 0 ----
    abuf = *(const float4*)(pfw + (size_t)(rt * 8 + r) * HID + (c << 2));
#pragma unroll
    for (int i = 0; i < 4; i++) {
        int k = sidx_k + i * 32;
        const float* p = value_w + (size_t)k * (HEADS * VSZ) + vt * 32 + sidx_c4;
#pragma unroll
        for (int h = 0; h < 4; h++) vbuf[i][h] = *(const float4*)(p + h * VSZ);
    }

    float acc0 = 0.f, acc1 = 0.f, acc2 = 0.f, acc3 = 0.f, s = 0.f;
    for (int kb = 0; kb < HID; kb += PKC) {
        __syncthreads();
        // ---- commit staged regs to smem ----
        *(float4*)&as[r][c << 2] = abuf;
#pragma unroll
        for (int i = 0; i < 4; i++) {
            int k = sidx_k + i * 32;
            float4 h0 = vbuf[i][0], h1 = vbuf[i][1], h2 = vbuf[i][2], h3 = vbuf[i][3];
            bs[k * BSX + sidx_c4 + 0] = 0.25f * (h0.x + h1.x + h2.x + h3.x);
            bs[k * BSX + sidx_c4 + 1] = 0.25f * (h0.y + h1.y + h2.y + h3.y);
            bs[k * BSX + sidx_c4 + 2] = 0.25f * (h0.z + h1.z + h2.z + h3.z);
            bs[k * BSX + sidx_c4 + 3] = 0.25f * (h0.w + h1.w + h2.w + h3.w);
        }
        __syncthreads();

        // ---- prefetch next chunk while computing this one ----
        if (kb + PKC < HID) {
            int kn = kb + PKC;
            abuf = *(const float4*)(pfw + (size_t)(rt * 8 + r) * HID + kn + (c << 2));
#pragma unroll
            for (int i = 0; i < 4; i++) {
                int k = kn + sidx_k + i * 32;
                const float* p = value_w + (size_t)k * (HEADS * VSZ) + vt * 32 + sidx_c4;
#pragma unroll
                for (int h = 0; h < 4; h++) vbuf[i][h] = *(const float4*)(p + h * VSZ);
            }
        }

        // ---- compute: 4 split accumulators (no long RAW chain) ----
#pragma unroll 8
        for (int k4 = 0; k4 < PKC / 4; k4++) {
            float4 a = *(float4*)&as[r][k4 * 4];
            acc0 += a.x * bs[(k4 * 4 + 0) * BSX + c];
            acc1 += a.y * bs[(k4 * 4 + 1) * BSX + c];
            acc2 += a.z * bs[(k4 * 4 + 2) * BSX + c];
            acc3 += a.w * bs[(k4 * 4 + 3) * BSX + c];
        }
        if (do_c0) {
#pragma unroll
            for (int i = 0; i < 16; i++) {
                int kl = r * 16 + i;
                s += pfb[kb + kl] * bs[kl * BSX + c];
            }
        }
    }
    g_weff[(size_t)(rt * 8 + r) * VSZ + vt * 32 + c] = (acc0 + acc1) + (acc2 + acc3);

    if (do_c0) {
        red[t] = s;
        __syncthreads();
        if (t < 32) {
            float ss = 0.f;
#pragma unroll
            for (int m = 0; m < 8; m++) ss += red[t + 32 * m];
            int col = vt * 32 + t;
            float bb = 0.25f * (value_b[col] + value_b[VSZ + col] +
                                value_b[2 * VSZ + col] + value_b[3 * VSZ + col]);
            g_bb[col] = bb;
            g_c0[col] = ss + bb;
        }
    }
}

// ===================== K2: main GEMM ======================================
// out[b,v] = A[opt_b] * (x_b . W_eff[:,v] + c0[v]) + C[opt_b] * bb[v]
// 128 blocks x 1024 threads; tile 64 rows x 256 cols; per-thread 2r x 8c.
// x staged DUPLICATED in smem -> inner loop: LDS.64 broadcast + FFMA2, no movs.
#define KXD 264   // dup row stride (floats): 256 + 8 pad, 16B aligned
#define WSK 32    // W k-chunk

#define FMA2(acc, a, b) \
    asm("fma.rn.f32x2 %0, %1, %2, %0;" : "+l"(acc) : "l"(a), "l"(b))

__global__ __launch_bounds__(1024)
void main_gemm(const float* __restrict__ x, const int* __restrict__ opt,
               float* __restrict__ out) {
    extern __shared__ float sm[];
    float* ws  = sm;                    // 32 k x 256 v
    float* xsd = ws + WSK * VSZ;        // 64 rows x KXD (duplicated pairs)
    float* sA  = xsd + 64 * KXD;        // 64
    float* sC  = sA + 64;               // 64
    float* sc0 = sC + 64;               // 256
    float* sbb = sc0 + VSZ;             // 256

    int t  = threadIdx.x;
    int rb = blockIdx.x * 64;
    int rg = t >> 5;                    // warp id: rows rg*2, rg*2+1
    int cg = t & 31;                    // cols cg*8 .. +7

    // ---- stage x duplicated: 2048 source float4, 2 per thread ----
#pragma unroll
    for (int i = 0; i < 2; i++) {
        int idx = t + i * 1024;
        int r = idx >> 5, k4 = (idx & 31) << 2;
        float4 v = *(const float4*)(x + (size_t)(rb + r) * OBS + k4);
        float* d = &xsd[r * KXD + 2 * k4];
        *(float4*)(d + 0) = make_float4(v.x, v.x, v.y, v.y);
        *(float4*)(d + 4) = make_float4(v.z, v.z, v.w, v.w);
    }
    if (t < 64) {
        int o = opt[rb + t];
        sA[t] = g_A[o];
        sC[t] = g_C[o];
    }
    if (t >= 1024 - 256) {
        int c = t - (1024 - 256);
        sc0[c] = g_c0[c];
        sbb[c] = g_bb[c];
    }

    unsigned long long acc[2][4];       // [row][col-pair]
#pragma unroll
    for (int i = 0; i < 2; i++)
#pragma unroll
        for (int q = 0; q < 4; q++) acc[i][q] = 0ull;

    const float* x0 = &xsd[(rg * 2 + 0) * KXD];
    const float* x1 = &xsd[(rg * 2 + 1) * KXD];

    for (int kb = 0; kb < OBS; kb += WSK) {
        __syncthreads();
        // ---- stage W chunk [32 k x 256 v]: 2048 float4, 2 per thread ----
#pragma unroll
        for (int i = 0; i < 2; i++) {
            int idx = t + i * 1024;
            *(float4*)&ws[idx * 4] =
                *(const float4*)(g_weff + (size_t)kb * VSZ + idx * 4);
        }
        __syncthreads();

#pragma unroll 8
        for (int k = 0; k < WSK; k++) {
            ulonglong2 w0 = *(const ulonglong2*)&ws[k * VSZ + cg * 8];
            ulonglong2 w1 = *(const ulonglong2*)&ws[k * VSZ + cg * 8 + 4];
            unsigned long long a0 = *(const unsigned long long*)(x0 + 2 * (kb + k));
            unsigned long long a1 = *(const unsigned long long*)(x1 + 2 * (kb + k));
            FMA2(acc[0][0], a0, w0.x); FMA2(acc[0][1], a0, w0.y);
            FMA2(acc[0][2], a0, w1.x); FMA2(acc[0][3], a0, w1.y);
            FMA2(acc[1][0], a1, w0.x); FMA2(acc[1][1], a1, w0.y);
            FMA2(acc[1][2], a1, w1.x); FMA2(acc[1][3], a1, w1.y);
        }
    }

    // ---- epilogue ----
#pragma unroll
    for (int i = 0; i < 2; i++) {
        int rl  = rg * 2 + i;
        float Ar = sA[rl], Cr = sC[rl];
        float* orow = out + (size_t)(rb + rl) * VSZ + cg * 8;
#pragma unroll
        for (int half = 0; half < 2; half++) {
            int c = cg * 8 + half * 4;
            unsigned int u0, u1, u2, u3;
            asm("mov.b64 {%0,%1}, %2;" : "=r"(u0), "=r"(u1) : "l"(acc[i][half * 2 + 0]));
            asm("mov.b64 {%0,%1}, %2;" : "=r"(u2), "=r"(u3) : "l"(acc[i][half * 2 + 1]));
            float4 o4;
            o4.x = Ar * (__uint_as_float(u0) + sc0[c + 0]) + Cr * sbb[c + 0];
            o4.y = Ar * (__uint_as_float(u1) + sc0[c + 1]) + Cr * sbb[c + 1];
            o4.z = Ar * (__uint_as_float(u2) + sc0[c + 2]) + Cr * sbb[c + 2];
            o4.w = Ar * (__uint_as_float(u3) + sc0[c + 3]) + Cr * sbb[c + 3];
            *(float4*)(orow + half * 4) = o4;
        }
    }
}

// ---------------- launch ---------------------------------------------------
extern "C" void kernel_launch(void* const* d_in, const int* in_sizes, int n_in,
                              void* d_out, int out_size) {
    (void)in_sizes; (void)n_in; (void)out_size;
    const float* x        = (const float*)d_in[0];
    const int*   option   = (const int*)  d_in[1];
    const float* pre_fc_w = (const float*)d_in[2];
    const float* pre_fc_b = (const float*)d_in[3];
    const float* value_w  = (const float*)d_in[4];
    const float* value_b  = (const float*)d_in[5];
    const float* p_w      = (const float*)d_in[6];
    const float* p_b      = (const float*)d_in[7];
    float* out = (float*)d_out;

    prep_all<<<dim3(8, 17), 256>>>(value_w, value_b, pre_fc_w, pre_fc_b, p_w, p_b);

    size_t smem = (WSK * VSZ + 64 * KXD + 64 + 64 + VSZ + VSZ) * sizeof(float);
    cudaFuncSetAttribute(main_gemm, cudaFuncAttributeMaxDynamicSharedMemorySize, (int)smem);
    main_gemm<<<128, 1024, smem>>>(x, option, out);
}

// round 13
// speedup vs baseline: 1.9814x; 1.9814x over previous
#include <cuda_runtime.h>
#include <cuda_bf16.h>
#include <mma.h>
#include <math.h>
#include <stdint.h>

using namespace nvcuda;

#define OBS  128
#define HID  512
#define VSZ  256
#define NU   64
#define TOPK 8
#define NOPT 16

// ---------------- device scratch (static, allocation-free) ----------------
__device__ float g_wp[4 * OBS * VSZ];     // k-split partials of W_eff (fp32)
__device__ float g_wpb[4 * VSZ];          // k-split partials of pfb . wbar
__device__ __align__(16) __nv_bfloat16 g_wh[OBS * VSZ];  // W_eff hi (row-major k x n)
__device__ __align__(16) __nv_bfloat16 g_wl[OBS * VSZ];  // W_eff lo
__device__ float g_c0[VSZ];
__device__ float g_bb[VSZ];
__device__ float g_A[NOPT];
__device__ float g_C[NOPT];

// ===================== prep1: k-split W_eff partials =======================
// grid (vt=8, rt=4, ks=4), block 256. Tile: o in [rt*32,+32), n in [vt*32,+32),
// k in [ks*128,+128). wbar head-meaned on the fly from value_w.
__global__ __launch_bounds__(256)
void prep1(const float* __restrict__ value_w, const float* __restrict__ pfw,
           const float* __restrict__ pfb) {
    __shared__ float as[32][132];
    __shared__ float bs[128 * 33];
    int vt = blockIdx.x, rt = blockIdx.y, ks = blockIdx.z;
    int t = threadIdx.x;

#pragma unroll
    for (int i = 0; i < 4; i++) {
        int idx = t + i * 256;              // 1024
        int k = idx >> 3, c4 = (idx & 7) << 2;
        const float* p = value_w + (size_t)(ks * 128 + k) * (4 * VSZ) + vt * 32 + c4;
        float4 h0 = *(const float4*)p;
        float4 h1 = *(const float4*)(p + VSZ);
        float4 h2 = *(const float4*)(p + 2 * VSZ);
        float4 h3 = *(const float4*)(p + 3 * VSZ);
        bs[k * 33 + c4 + 0] = 0.25f * (h0.x + h1.x + h2.x + h3.x);
        bs[k * 33 + c4 + 1] = 0.25f * (h0.y + h1.y + h2.y + h3.y);
        bs[k * 33 + c4 + 2] = 0.25f * (h0.z + h1.z + h2.z + h3.z);
        bs[k * 33 + c4 + 3] = 0.25f * (h0.w + h1.w + h2.w + h3.w);
    }
#pragma unroll
    for (int i = 0; i < 4; i++) {
        int idx = t + i * 256;
        int o = idx >> 5, k4 = (idx & 31) << 2;
        *(float4*)&as[o][k4] =
            *(const float4*)(pfw + (size_t)(rt * 32 + o) * HID + ks * 128 + k4);
    }
    __syncthreads();

    int n = t & 31, og = t >> 5;
    float acc[4] = {0.f, 0.f, 0.f, 0.f};
#pragma unroll 4
    for (int k4 = 0; k4 < 32; k4++) {
        float b0 = bs[(k4 * 4 + 0) * 33 + n];
        float b1 = bs[(k4 * 4 + 1) * 33 + n];
        float b2 = bs[(k4 * 4 + 2) * 33 + n];
        float b3 = bs[(k4 * 4 + 3) * 33 + n];
#pragma unroll
        for (int i = 0; i < 4; i++) {
            float4 a = *(float4*)&as[og * 4 + i][k4 * 4];
            acc[i] += a.x * b0 + a.y * b1 + a.z * b2 + a.w * b3;
        }
    }
#pragma unroll
    for (int i = 0; i < 4; i++)
        g_wp[(size_t)ks * (OBS * VSZ) + (size_t)(rt * 32 + og * 4 + i) * VSZ + vt * 32 + n] = acc[i];

    if (rt == 0 && t < 32) {
        float s = 0.f;
        for (int k = 0; k < 128; k++) s += pfb[ks * 128 + k] * bs[k * 33 + t];
        g_wpb[ks * VSZ + vt * 32 + t] = s;
    }
}

// ===================== prep2: reduce + bf16 split + scalars ================
// blocks 0..63: reduce W_eff partials, split hi/lo bf16 (row-major [k][n]).
// block 64: c0/bbar + per-option top-k scalars.
__global__ __launch_bounds__(256)
void prep2(const float* __restrict__ value_b, const float* __restrict__ p_w,
           const float* __restrict__ p_b) {
    int b = blockIdx.x, t = threadIdx.x;

    if (b < 64) {
        int idx = b * 256 + t;              // 16384 bf16x2 pairs
        int lin = idx * 2;                  // element index (k*256 + n)
        float w0 = 0.f, w1 = 0.f;
#pragma unroll
        for (int ks = 0; ks < 4; ks++) {
            const float* p = g_wp + (size_t)ks * (OBS * VSZ) + lin;
            w0 += p[0];
            w1 += p[1];
        }
        __nv_bfloat16 h0 = __float2bfloat16(w0);
        __nv_bfloat16 h1 = __float2bfloat16(w1);
        __nv_bfloat162 hv; hv.x = h0; hv.y = h1;
        __nv_bfloat162 lv;
        lv.x = __float2bfloat16(w0 - __bfloat162float(h0));
        lv.y = __float2bfloat16(w1 - __bfloat162float(h1));
        *(__nv_bfloat162*)(g_wh + lin) = hv;
        *(__nv_bfloat162*)(g_wl + lin) = lv;
        return;
    }

    // b == 64
    {
        float s = g_wpb[t] + g_wpb[VSZ + t] + g_wpb[2 * VSZ + t] + g_wpb[3 * VSZ + t];
        float bb = 0.25f * (value_b[t] + value_b[VSZ + t] +
                            value_b[2 * VSZ + t] + value_b[3 * VSZ + t]);
        g_bb[t] = bb;
        g_c0[t] = s + bb;
    }
    int lane = t & 31, w = t >> 5;
    for (int o = w; o < NOPT; o += 8) {
        float v0 = p_w[o * NU + lane] + p_b[lane];
        float v1 = p_w[o * NU + 32 + lane] + p_b[32 + lane];
        float ssum = 0.f;
#pragma unroll
        for (int it = 0; it < TOPK; it++) {
            float mv; int mi;
            if (v0 >= v1) { mv = v0; mi = lane; } else { mv = v1; mi = lane + 32; }
#pragma unroll
            for (int off = 16; off; off >>= 1) {
                float ov = __shfl_xor_sync(0xffffffffu, mv, off);
                int   oi = __shfl_xor_sync(0xffffffffu, mi, off);
                if (ov > mv || (ov == mv && oi < mi)) { mv = ov; mi = oi; }
            }
            ssum += 1.f / (1.f + expf(-mv));
            if (mi == lane)           v0 = -1e30f;
            else if (mi == lane + 32) v1 = -1e30f;
        }
        if (lane == 0) {
            g_A[o] = ssum * (1.f / 64.f);
            g_C[o] = (8.f - ssum) * (1.f / 64.f);
        }
    }
}

// ===================== main: wmma bf16 3-pass GEMM =========================
// 128 CTAs x 512 threads. Tile 64 rows x 256 cols, K=128 per pass, 3 passes:
// D = xh@wh + xh@wl + xl@wh (fp32 accum). Epilogue: + A*c0 + C*bb.
// Warp grid 2x8: warp_m = wid&1 (32 rows), warp_n = wid>>1 (32 cols).
#define XAS 136   // x smem stride (bf16 els): 272 B, 16B-mult
#define WBS 264   // W smem stride (bf16 els): 528 B, 16B-mult
#define OBS_S 264 // out buffer stride (fp32 els)

// smem layout (bytes)
#define SM_XH 0
#define SM_XL (SM_XH + 64 * XAS * 2)         // 17408
#define SM_WH (SM_XL + 64 * XAS * 2)         // 34816
#define SM_WL (SM_WH + 128 * WBS * 2)        // 102400
#define SM_SA (SM_WL + 128 * WBS * 2)        // 169984
#define SM_SC (SM_SA + 256)
#define SM_C0 (SM_SC + 256)
#define SM_BB (SM_C0 + 1024)
#define SMEM_MAIN (SM_BB + 1024)             // 172544
#define SM_OUT SM_WH                          // aliases wh (dead after GEMM)

__global__ __launch_bounds__(512, 1)
void main_mma(const float* __restrict__ x, const int* __restrict__ opt,
              float* __restrict__ out) {
    extern __shared__ char smem[];
    __nv_bfloat16* xh_s = (__nv_bfloat16*)(smem + SM_XH);
    __nv_bfloat16* xl_s = (__nv_bfloat16*)(smem + SM_XL);
    __nv_bfloat16* wh_s = (__nv_bfloat16*)(smem + SM_WH);
    __nv_bfloat16* wl_s = (__nv_bfloat16*)(smem + SM_WL);
    float* sA  = (float*)(smem + SM_SA);
    float* sC  = (float*)(smem + SM_SC);
    float* sc0 = (float*)(smem + SM_C0);
    float* sbb = (float*)(smem + SM_BB);
    float* obuf = (float*)(smem + SM_OUT);

    int t  = threadIdx.x;
    int rb = blockIdx.x * 64;

    // ---- per-row scales first (needed by x staging) ----
    if (t < 64) {
        int o = opt[rb + t];
        sA[t] = g_A[o];
        sC[t] = g_C[o];
    }
    if (t >= 256 && t < 512) {
        int c = t - 256;
        sc0[c] = g_c0[c];
        sbb[c] = g_bb[c];
    }
    __syncthreads();

    // ---- stage W hi/lo: 4096 uint4 each, 8 per thread ----
#pragma unroll
    for (int i = 0; i < 8; i++) {
        int idx = t + i * 512;
        int r = idx >> 5, c8 = (idx & 31) << 3;
        *(uint4*)(wh_s + r * WBS + c8) = ((const uint4*)g_wh)[idx];
        *(uint4*)(wl_s + r * WBS + c8) = ((const uint4*)g_wl)[idx];
    }
    // ---- stage x scaled + hi/lo split: 2048 float4, 4 per thread ----
#pragma unroll
    for (int i = 0; i < 4; i++) {
        int idx = t + i * 512;
        int r = idx >> 5, k4 = (idx & 31) << 2;
        float4 v = *(const float4*)(x + (size_t)(rb + r) * OBS + k4);
        float a = sA[r];
        float f0 = v.x * a, f1 = v.y * a, f2 = v.z * a, f3 = v.w * a;
        __nv_bfloat16 h0 = __float2bfloat16(f0), h1 = __float2bfloat16(f1);
        __nv_bfloat16 h2 = __float2bfloat16(f2), h3 = __float2bfloat16(f3);
        __nv_bfloat16 l0 = __float2bfloat16(f0 - __bfloat162float(h0));
        __nv_bfloat16 l1 = __float2bfloat16(f1 - __bfloat162float(h1));
        __nv_bfloat16 l2 = __float2bfloat16(f2 - __bfloat162float(h2));
        __nv_bfloat16 l3 = __float2bfloat16(f3 - __bfloat162float(h3));
        __nv_bfloat16* dh = xh_s + r * XAS + k4;
        __nv_bfloat16* dl = xl_s + r * XAS + k4;
        dh[0] = h0; dh[1] = h1; dh[2] = h2; dh[3] = h3;
        dl[0] = l0; dl[1] = l1; dl[2] = l2; dl[3] = l3;
    }
    __syncthreads();

    // ---- wmma 3-pass GEMM ----
    int wid = t >> 5;
    int wm = (wid & 1) * 32;        // row base within tile
    int wn = (wid >> 1) * 32;       // col base

    wmma::fragment<wmma::accumulator, 16, 16, 16, float> acc[2][2];
#pragma unroll
    for (int i = 0; i < 2; i++)
#pragma unroll
        for (int j = 0; j < 2; j++) wmma::fill_fragment(acc[i][j], 0.0f);

#pragma unroll
    for (int ph = 0; ph < 3; ph++) {
        const __nv_bfloat16* As = (ph == 2) ? xl_s : xh_s;
        const __nv_bfloat16* Bs = (ph == 1) ? wl_s : wh_s;
#pragma unroll
        for (int kk = 0; kk < 128; kk += 16) {
            wmma::fragment<wmma::matrix_a, 16, 16, 16, __nv_bfloat16, wmma::row_major> a0, a1;
            wmma::fragment<wmma::matrix_b, 16, 16, 16, __nv_bfloat16, wmma::row_major> b0, b1;
            wmma::load_matrix_sync(a0, As + (wm +  0) * XAS + kk, XAS);
            wmma::load_matrix_sync(a1, As + (wm + 16) * XAS + kk, XAS);
            wmma::load_matrix_sync(b0, Bs + kk * WBS + wn +  0, WBS);
            wmma::load_matrix_sync(b1, Bs + kk * WBS + wn + 16, WBS);
            wmma::mma_sync(acc[0][0], a0, b0, acc[0][0]);
            wmma::mma_sync(acc[0][1], a0, b1, acc[0][1]);
            wmma::mma_sync(acc[1][0], a1, b0, acc[1][0]);
            wmma::mma_sync(acc[1][1], a1, b1, acc[1][1]);
        }
    }

    // ---- park accumulators in smem (aliases dead wh region) ----
    __syncthreads();
#pragma unroll
    for (int i = 0; i < 2; i++)
#pragma unroll
        for (int j = 0; j < 2; j++)
            wmma::store_matrix_sync(obuf + (wm + i * 16) * OBS_S + wn + j * 16,
                                    acc[i][j], OBS_S, wmma::mem_row_major);
    __syncthreads();

    // ---- finalize: out = obuf + A*c0 + C*bb ----
#pragma unroll
    for (int i = 0; i < 8; i++) {
        int idx = t + i * 512;              // 4096 float4 groups
        int r = idx >> 6, c4 = (idx & 63) << 2;
        float Ar = sA[r], Cr = sC[r];
        const float* src = obuf + r * OBS_S + c4;
        float4 o4;
        o4.x = src[0] + Ar * sc0[c4 + 0] + Cr * sbb[c4 + 0];
        o4.y = src[1] + Ar * sc0[c4 + 1] + Cr * sbb[c4 + 1];
        o4.z = src[2] + Ar * sc0[c4 + 2] + Cr * sbb[c4 + 2];
        o4.w = src[3] + Ar * sc0[c4 + 3] + Cr * sbb[c4 + 3];
        *(float4*)(out + (size_t)(rb + r) * VSZ + c4) = o4;
    }
}

// ---------------- launch ---------------------------------------------------
extern "C" void kernel_launch(void* const* d_in, const int* in_sizes, int n_in,
                              void* d_out, int out_size) {
    (void)in_sizes; (void)n_in; (void)out_size;
    const float* x        = (const float*)d_in[0];
    const int*   option   = (const int*)  d_in[1];
    const float* pre_fc_w = (const float*)d_in[2];
    const float* pre_fc_b = (const float*)d_in[3];
    const float* value_w  = (const float*)d_in[4];
    const float* value_b  = (const float*)d_in[5];
    const float* p_w      = (const float*)d_in[6];
    const float* p_b      = (const float*)d_in[7];
    float* out = (float*)d_out;

    prep1<<<dim3(8, 4, 4), 256>>>(value_w, pre_fc_w, pre_fc_b);
    prep2<<<65, 256>>>(value_b, p_w, p_b);

    cudaFuncSetAttribute(main_mma, cudaFuncAttributeMaxDynamicSharedMemorySize, SMEM_MAIN);
    main_mma<<<128, 512, SMEM_MAIN>>>(x, option, out);
}

// round 15
// speedup vs baseline: 2.0033x; 1.0111x over previous
#include <cuda_runtime.h>
#include <cuda_bf16.h>
#include <mma.h>
#include <math.h>
#include <stdint.h>

using namespace nvcuda;

#define OBS  128
#define HID  512
#define VSZ  256
#define NU   64
#define TOPK 8
#define NOPT 16

// ---------------- device scratch (static, allocation-free) ----------------
__device__ __align__(16) __nv_bfloat16 g_wbh[HID * VSZ];  // wbar hi (k x n)
__device__ __align__(16) __nv_bfloat16 g_wbl[HID * VSZ];  // wbar lo
__device__ __align__(16) __nv_bfloat16 g_wh[OBS * VSZ];   // W_eff hi (k x n)
__device__ __align__(16) __nv_bfloat16 g_wl[OBS * VSZ];   // W_eff lo
__device__ float g_c0[VSZ];
__device__ float g_bb[VSZ];
__device__ float g_A[NOPT];
__device__ float g_C[NOPT];

__device__ __forceinline__ void split_bf16(float v, __nv_bfloat16& h, __nv_bfloat16& l) {
    h = __float2bfloat16(v);
    l = __float2bfloat16(v - __bfloat162float(h));
}

// ===================== prepA: coalesced wbar split + scalars ===============
// blocks 0..127: 4 wbar rows each (fully coalesced reads of value_w).
// block 128: bbar + per-option top-k scalars.
__global__ __launch_bounds__(256)
void prepA(const float* __restrict__ value_w, const float* __restrict__ value_b,
           const float* __restrict__ p_w, const float* __restrict__ p_b) {
    int b = blockIdx.x, t = threadIdx.x;

    if (b < 128) {
        int r  = b * 4 + (t >> 6);          // 4 rows, 64 threads/row
        int n4 = (t & 63) * 4;
        const float* p = value_w + (size_t)r * (4 * VSZ) + n4;
        float4 h0 = *(const float4*)(p);
        float4 h1 = *(const float4*)(p + VSZ);
        float4 h2 = *(const float4*)(p + 2 * VSZ);
        float4 h3 = *(const float4*)(p + 3 * VSZ);
        float m0 = 0.25f * (h0.x + h1.x + h2.x + h3.x);
        float m1 = 0.25f * (h0.y + h1.y + h2.y + h3.y);
        float m2 = 0.25f * (h0.z + h1.z + h2.z + h3.z);
        float m3 = 0.25f * (h0.w + h1.w + h2.w + h3.w);
        __nv_bfloat162 ha, hb, la, lb;
        split_bf16(m0, ha.x, la.x); split_bf16(m1, ha.y, la.y);
        split_bf16(m2, hb.x, lb.x); split_bf16(m3, hb.y, lb.y);
        __nv_bfloat162* dh = (__nv_bfloat162*)(g_wbh + (size_t)r * VSZ + n4);
        __nv_bfloat162* dl = (__nv_bfloat162*)(g_wbl + (size_t)r * VSZ + n4);
        dh[0] = ha; dh[1] = hb;
        dl[0] = la; dl[1] = lb;
        return;
    }

    // b == 128: bbar + scalars
    g_bb[t] = 0.25f * (value_b[t] + value_b[VSZ + t] +
                       value_b[2 * VSZ + t] + value_b[3 * VSZ + t]);
    int lane = t & 31, w = t >> 5;
    for (int o = w; o < NOPT; o += 8) {
        float v0 = p_w[o * NU + lane] + p_b[lane];
        float v1 = p_w[o * NU + 32 + lane] + p_b[32 + lane];
        float ssum = 0.f;
#pragma unroll
        for (int it = 0; it < TOPK; it++) {
            float mv; int mi;
            if (v0 >= v1) { mv = v0; mi = lane; } else { mv = v1; mi = lane + 32; }
#pragma unroll
            for (int off = 16; off; off >>= 1) {
                float ov = __shfl_xor_sync(0xffffffffu, mv, off);
                int   oi = __shfl_xor_sync(0xffffffffu, mi, off);
                if (ov > mv || (ov == mv && oi < mi)) { mv = ov; mi = oi; }
            }
            ssum += 1.f / (1.f + expf(-mv));
            if (mi == lane)           v0 = -1e30f;
            else if (mi == lane + 32) v1 = -1e30f;
        }
        if (lane == 0) {
            g_A[o] = ssum * (1.f / 64.f);
            g_C[o] = (8.f - ssum) * (1.f / 64.f);
        }
    }
}

// ===================== prepB: W_eff via wmma 3-pass + c0 ===================
// grid (8 nt, 8 rt) = 64 blocks, 256 threads. Tile: 16 rows x 32 cols, K=512.
// 8 warps k-split (64 k each), fp32 frags reduced via smem. rt==0 also c0.
#define PAS 520   // a smem stride (bf16)
#define PBS 40    // b smem stride (bf16)
#define POS 40    // obuf stride (fp32)

// smem layout (bytes)
#define PB_AH 0
#define PB_AL (PB_AH + 16 * PAS * 2)          // 16640
#define PB_BH (PB_AL + 16 * PAS * 2)          // 33280
#define PB_BL (PB_BH + HID * PBS * 2)         // 74240
#define PB_RED (PB_BL + HID * PBS * 2)        // 115200
#define PB_SMEM (PB_RED + 1024)               // 116224
#define PB_OBUF PB_AH                          // aliases a region (8*16*40*4=20480 <= 33280)

__global__ __launch_bounds__(256)
void prepB(const float* __restrict__ pfw, const float* __restrict__ pfb) {
    extern __shared__ char sm[];
    __nv_bfloat16* ah = (__nv_bfloat16*)(sm + PB_AH);
    __nv_bfloat16* al = (__nv_bfloat16*)(sm + PB_AL);
    __nv_bfloat16* bh = (__nv_bfloat16*)(sm + PB_BH);
    __nv_bfloat16* bl = (__nv_bfloat16*)(sm + PB_BL);
    float* red  = (float*)(sm + PB_RED);
    float* obuf = (float*)(sm + PB_OBUF);

    int nt = blockIdx.x, rt = blockIdx.y;
    int t = threadIdx.x;

    // stage A (pfw rows rt*16..+16, K=512) split hi/lo: 2048 float4
#pragma unroll
    for (int i = 0; i < 8; i++) {
        int idx = t + i * 256;
        int r = idx >> 7, k4 = (idx & 127) << 2;
        float4 v = *(const float4*)(pfw + (size_t)(rt * 16 + r) * HID + k4);
        __nv_bfloat16 h0, h1, h2, h3, l0, l1, l2, l3;
        split_bf16(v.x, h0, l0); split_bf16(v.y, h1, l1);
        split_bf16(v.z, h2, l2); split_bf16(v.w, h3, l3);
        __nv_bfloat16* dh = ah + r * PAS + k4;
        __nv_bfloat16* dl = al + r * PAS + k4;
        dh[0] = h0; dh[1] = h1; dh[2] = h2; dh[3] = h3;
        dl[0] = l0; dl[1] = l1; dl[2] = l2; dl[3] = l3;
    }
    // stage B (wbar cols nt*32..+32, all 512 rows): 2048 uint4 each
#pragma unroll
    for (int i = 0; i < 8; i++) {
        int idx = t + i * 256;
        int r = idx >> 2, c8 = (idx & 3) << 3;
        *(uint4*)(bh + r * PBS + c8) = *(const uint4*)(g_wbh + (size_t)r * VSZ + nt * 32 + c8);
        *(uint4*)(bl + r * PBS + c8) = *(const uint4*)(g_wbl + (size_t)r * VSZ + nt * 32 + c8);
    }
    __syncthreads();

    // c0 partials FIRST (uses bh/bl which stay live): warp w -> k slab, col=lane
    int wid = t >> 5, lane = t & 31;
    if (rt == 0) {
        float s = 0.f;
#pragma unroll 4
        for (int i = 0; i < 64; i++) {
            int k = wid * 64 + i;
            s += pfb[k] * (__bfloat162float(bh[k * PBS + lane]) +
                           __bfloat162float(bl[k * PBS + lane]));
        }
        red[t] = s;
    }

    // wmma: warp wid handles k in [wid*64, +64), 3 passes, 1x2 frags
    wmma::fragment<wmma::accumulator, 16, 16, 16, float> acc[2];
    wmma::fill_fragment(acc[0], 0.0f);
    wmma::fill_fragment(acc[1], 0.0f);
#pragma unroll
    for (int ph = 0; ph < 3; ph++) {
        const __nv_bfloat16* As = (ph == 2) ? al : ah;
        const __nv_bfloat16* Bs = (ph == 1) ? bl : bh;
#pragma unroll
        for (int kk = 0; kk < 64; kk += 16) {
            int k = wid * 64 + kk;
            wmma::fragment<wmma::matrix_a, 16, 16, 16, __nv_bfloat16, wmma::row_major> af;
            wmma::fragment<wmma::matrix_b, 16, 16, 16, __nv_bfloat16, wmma::row_major> b0, b1;
            wmma::load_matrix_sync(af, As + k, PAS);
            wmma::load_matrix_sync(b0, Bs + k * PBS, PBS);
            wmma::load_matrix_sync(b1, Bs + k * PBS + 16, PBS);
            wmma::mma_sync(acc[0], af, b0, acc[0]);
            wmma::mma_sync(acc[1], af, b1, acc[1]);
        }
    }
    __syncthreads();   // a region dead -> reuse as obuf
    wmma::store_matrix_sync(obuf + wid * 16 * POS,      acc[0], POS, wmma::mem_row_major);
    wmma::store_matrix_sync(obuf + wid * 16 * POS + 16, acc[1], POS, wmma::mem_row_major);
    __syncthreads();

    // reduce 8 warp-slabs, split hi/lo, write
#pragma unroll
    for (int i = 0; i < 2; i++) {
        int e = t + i * 256;           // 512 outputs
        int r = e >> 5, c = e & 31;
        float s = 0.f;
#pragma unroll
        for (int w = 0; w < 8; w++) s += obuf[w * 16 * POS + r * POS + c];
        __nv_bfloat16 h, l;
        split_bf16(s, h, l);
        size_t off = (size_t)(rt * 16 + r) * VSZ + nt * 32 + c;
        g_wh[off] = h;
        g_wl[off] = l;
    }

    if (rt == 0 && t < 32) {
        float s = 0.f;
#pragma unroll
        for (int w = 0; w < 8; w++) s += red[w * 32 + t];
        int col = nt * 32 + t;
        g_c0[col] = s + g_bb[col];
    }
}

// ===================== main: wmma bf16 3-pass GEMM =========================
// 128 CTAs x 512 threads. Tile 64 rows x 256 cols, K=128, 3 passes:
// D = xh@wh + xh@wl + xl@wh (fp32 accum). Epilogue: + A*c0 + C*bb.
#define XAS 136
#define WBS 264
#define OBS_S 264

#define SM_XH 0
#define SM_XL (SM_XH + 64 * XAS * 2)
#define SM_WH (SM_XL + 64 * XAS * 2)
#define SM_WL (SM_WH + 128 * WBS * 2)
#define SM_SA (SM_WL + 128 * WBS * 2)
#define SM_SC (SM_SA + 256)
#define SM_C0 (SM_SC + 256)
#define SM_BB (SM_C0 + 1024)
#define SMEM_MAIN (SM_BB + 1024)
#define SM_OUT SM_WH

__global__ __launch_bounds__(512, 1)
void main_mma(const float* __restrict__ x, const int* __restrict__ opt,
              float* __restrict__ out) {
    extern __shared__ char smem[];
    __nv_bfloat16* xh_s = (__nv_bfloat16*)(smem + SM_XH);
    __nv_bfloat16* xl_s = (__nv_bfloat16*)(smem + SM_XL);
    __nv_bfloat16* wh_s = (__nv_bfloat16*)(smem + SM_WH);
    __nv_bfloat16* wl_s = (__nv_bfloat16*)(smem + SM_WL);
    float* sA  = (float*)(smem + SM_SA);
    float* sC  = (float*)(smem + SM_SC);
    float* sc0 = (float*)(smem + SM_C0);
    float* sbb = (float*)(smem + SM_BB);
    float* obuf = (float*)(smem + SM_OUT);

    int t  = threadIdx.x;
    int rb = blockIdx.x * 64;

    if (t < 64) {
        int o = opt[rb + t];
        sA[t] = g_A[o];
        sC[t] = g_C[o];
    }
    if (t >= 256 && t < 512) {
        int c = t - 256;
        sc0[c] = g_c0[c];
        sbb[c] = g_bb[c];
    }
    __syncthreads();

#pragma unroll
    for (int i = 0; i < 8; i++) {
        int idx = t + i * 512;
        int r = idx >> 5, c8 = (idx & 31) << 3;
        *(uint4*)(wh_s + r * WBS + c8) = ((const uint4*)g_wh)[idx];
        *(uint4*)(wl_s + r * WBS + c8) = ((const uint4*)g_wl)[idx];
    }
#pragma unroll
    for (int i = 0; i < 4; i++) {
        int idx = t + i * 512;
        int r = idx >> 5, k4 = (idx & 31) << 2;
        float4 v = *(const float4*)(x + (size_t)(rb + r) * OBS + k4);
        float a = sA[r];
        float f0 = v.x * a, f1 = v.y * a, f2 = v.z * a, f3 = v.w * a;
        __nv_bfloat16 h0, h1, h2, h3, l0, l1, l2, l3;
        split_bf16(f0, h0, l0); split_bf16(f1, h1, l1);
        split_bf16(f2, h2, l2); split_bf16(f3, h3, l3);
        __nv_bfloat16* dh = xh_s + r * XAS + k4;
        __nv_bfloat16* dl = xl_s + r * XAS + k4;
        dh[0] = h0; dh[1] = h1; dh[2] = h2; dh[3] = h3;
        dl[0] = l0; dl[1] = l1; dl[2] = l2; dl[3] = l3;
    }
    __syncthreads();

    int wid = t >> 5;
    int wm = (wid & 1) * 32;
    int wn = (wid >> 1) * 32;

    wmma::fragment<wmma::accumulator, 16, 16, 16, float> acc[2][2];
#pragma unroll
    for (int i = 0; i < 2; i++)
#pragma unroll
        for (int j = 0; j < 2; j++) wmma::fill_fragment(acc[i][j], 0.0f);

#pragma unroll
    for (int ph = 0; ph < 3; ph++) {
        const __nv_bfloat16* As = (ph == 2) ? xl_s : xh_s;
        const __nv_bfloat16* Bs = (ph == 1) ? wl_s : wh_s;
#pragma unroll
        for (int kk = 0; kk < 128; kk += 16) {
            wmma::fragment<wmma::matrix_a, 16, 16, 16, __nv_bfloat16, wmma::row_major> a0, a1;
            wmma::fragment<wmma::matrix_b, 16, 16, 16, __nv_bfloat16, wmma::row_major> b0, b1;
            wmma::load_matrix_sync(a0, As + (wm +  0) * XAS + kk, XAS);
            wmma::load_matrix_sync(a1, As + (wm + 16) * XAS + kk, XAS);
            wmma::load_matrix_sync(b0, Bs + kk * WBS + wn +  0, WBS);
            wmma::load_matrix_sync(b1, Bs + kk * WBS + wn + 16, WBS);
            wmma::mma_sync(acc[0][0], a0, b0, acc[0][0]);
            wmma::mma_sync(acc[0][1], a0, b1, acc[0][1]);
            wmma::mma_sync(acc[1][0], a1, b0, acc[1][0]);
            wmma::mma_sync(acc[1][1], a1, b1, acc[1][1]);
        }
    }

    __syncthreads();
#pragma unroll
    for (int i = 0; i < 2; i++)
#pragma unroll
        for (int j = 0; j < 2; j++)
            wmma::store_matrix_sync(obuf + (wm + i * 16) * OBS_S + wn + j * 16,
                                    acc[i][j], OBS_S, wmma::mem_row_major);
    __syncthreads();

#pragma unroll
    for (int i = 0; i < 8; i++) {
        int idx = t + i * 512;
        int r = idx >> 6, c4 = (idx & 63) << 2;
        float Ar = sA[r], Cr = sC[r];
        const float* src = obuf + r * OBS_S + c4;
        float4 o4;
        o4.x = src[0] + Ar * sc0[c4 + 0] + Cr * sbb[c4 + 0];
        o4.y = src[1] + Ar * sc0[c4 + 1] + Cr * sbb[c4 + 1];
        o4.z = src[2] + Ar * sc0[c4 + 2] + Cr * sbb[c4 + 2];
        o4.w = src[3] + Ar * sc0[c4 + 3] + Cr * sbb[c4 + 3];
        *(float4*)(out + (size_t)(rb + r) * VSZ + c4) = o4;
    }
}

// ---------------- launch ---------------------------------------------------
extern "C" void kernel_launch(void* const* d_in, const int* in_sizes, int n_in,
                              void* d_out, int out_size) {
    (void)in_sizes; (void)n_in; (void)out_size;
    const float* x        = (const float*)d_in[0];
    const int*   option   = (const int*)  d_in[1];
    const float* pre_fc_w = (const float*)d_in[2];
    const float* pre_fc_b = (const float*)d_in[3];
    const float* value_w  = (const float*)d_in[4];
    const float* value_b  = (const float*)d_in[5];
    const float* p_w      = (const float*)d_in[6];
    const float* p_b      = (const float*)d_in[7];
    float* out = (float*)d_out;

    prepA<<<129, 256>>>(value_w, value_b, p_w, p_b);

    cudaFuncSetAttribute(prepB, cudaFuncAttributeMaxDynamicSharedMemorySize, PB_SMEM);
    prepB<<<dim3(8, 8), 256, PB_SMEM>>>(pre_fc_w, pre_fc_b);

    cudaFuncSetAttribute(main_mma, cudaFuncAttributeMaxDynamicSharedMemorySize, SMEM_MAIN);
    main_mma<<<128, 512, SMEM_MAIN>>>(x, option, out);
}